// round 11
// baseline (speedup 1.0000x reference)
#include <cuda_runtime.h>
#include <math.h>

#define NB 256
#define NC 64
#define NL 512
#define NLABS 10
#define EMBD 256
#define CINA 82
#define PT 37056
#define O_BH 16384
#define O_WL 16448
#define O_BL 20544
#define O_WS 20608
#define O_BS 36992
#define PIF 3.14159274101257324f

__device__ float g_yemb[NB * EMBD];
__device__ float g_p[(size_t)NB * PT];
__device__ float g_x[(size_t)NB * NC * NL];
__device__ float g_xs[(size_t)NB * NC * NL];
__device__ float g_d1[(size_t)NB * NC * NL];
__device__ float g_psum[NB * NC * 8];
__device__ float g_part[2048];

__device__ __forceinline__ float lrelu(float v) { return v > 0.f ? v : 0.2f * v; }

#define FMA2(d, a, b, c) asm("fma.rn.f32x2 %0, %1, %2, %3;" : "=l"(d) : "l"(a), "l"(b), "l"(c))
#define PACKDUP(d, f) { unsigned int _u = __float_as_uint(f); asm("mov.b64 %0, {%1, %2};" : "=l"(d) : "r"(_u), "r"(_u)); }
#define UNPK(lo, hi, v) { unsigned int _a, _b; asm("mov.b64 {%0, %1}, %2;" : "=r"(_a), "=r"(_b) : "l"(v)); lo = __uint_as_float(_a); hi = __uint_as_float(_b); }

// ---------------- yemb ----------------
__global__ void k_yemb(const float* __restrict__ fc_w, const float* __restrict__ fc_b,
                       const int* __restrict__ y) {
    int b = blockIdx.x, e = threadIdx.x;
    __shared__ float red[8];
    int lab = y[b];
    float v = fc_w[e * NLABS + lab] + fc_b[e];
    float ss = v * v;
#pragma unroll
    for (int o = 16; o; o >>= 1) ss += __shfl_xor_sync(0xffffffffu, ss, o);
    if ((e & 31) == 0) red[e >> 5] = ss;
    __syncthreads();
    if (e < 8) {
        float t = red[e];
#pragma unroll
        for (int o = 4; o; o >>= 1) t += __shfl_xor_sync(0xffu, t, o, 8);
        if (e == 0) red[0] = t;
    }
    __syncthreads();
    float nrm = fmaxf(sqrtf(red[0]), 1e-12f);
    g_yemb[b * EMBD + e] = v / nrm;
}

// ---------------- p = yemb @ hyper_w^T + hyper_b ----------------
__global__ void k_pgemm(const float* __restrict__ hw, const float* __restrict__ hb) {
    __shared__ float ys[64 * 65];
    __shared__ float wst[64 * 68];
    int j0 = blockIdx.x * 64, b0 = blockIdx.y * 64, tid = threadIdx.x;
    int jb = (tid & 15) * 4, bb = (tid >> 4) * 4;
    unsigned long long acc2[4][2];
#pragma unroll
    for (int v = 0; v < 4; v++) { acc2[v][0] = 0ull; acc2[v][1] = 0ull; }
    for (int e0 = 0; e0 < EMBD; e0 += 64) {
        __syncthreads();
        for (int idx = tid; idx < 4096; idx += 256) {
            int r = idx >> 6, e = idx & 63;
            ys[r * 65 + e] = g_yemb[(b0 + r) * EMBD + e0 + e];
            wst[e * 68 + r] = hw[(size_t)(j0 + r) * EMBD + e0 + e];
        }
        __syncthreads();
#pragma unroll 4
        for (int e = 0; e < 64; e++) {
            ulonglong2 wp = *(const ulonglong2*)(wst + e * 68 + jb);
#pragma unroll
            for (int v = 0; v < 4; v++) {
                unsigned long long y2;
                PACKDUP(y2, ys[(bb + v) * 65 + e]);
                FMA2(acc2[v][0], y2, wp.x, acc2[v][0]);
                FMA2(acc2[v][1], y2, wp.y, acc2[v][1]);
            }
        }
    }
#pragma unroll
    for (int v = 0; v < 4; v++) {
#pragma unroll
        for (int q = 0; q < 2; q++) {
            float lo, hi;
            UNPK(lo, hi, acc2[v][q]);
            size_t o = (size_t)(b0 + bb + v) * PT + j0 + jb + 2 * q;
            g_p[o] = lo + hb[j0 + jb + 2 * q];
            g_p[o + 1] = hi + hb[j0 + jb + 2 * q + 1];
        }
    }
}

// ---------------- fused input stage ----------------
__global__ void k_conv_in(const float* __restrict__ codes, const float* __restrict__ w0,
                          const float* __restrict__ b0, const float* __restrict__ ws) {
    __shared__ float xtr[16 * 132];
    __shared__ float xta[16 * 132];
    __shared__ float w0t[3][16 * 64];
    __shared__ float wst[16 * 64];
    int b = blockIdx.y, l0 = blockIdx.x * 128, tid = threadIdx.x;
    int lg = tid & 31, cg = tid >> 5;
    unsigned long long accd[4][4], accx[4][4];
#pragma unroll
    for (int p = 0; p < 4; p++)
#pragma unroll
        for (int d = 0; d < 4; d++) { accd[p][d] = 0ull; accx[p][d] = 0ull; }
    for (int ci0 = 0; ci0 < CINA; ci0 += 16) {
        int cs = min(16, CINA - ci0);
        __syncthreads();
        for (int idx = tid; idx < cs * 130; idx += 256) {
            int ci = idx / 130, j = idx - ci * 130;
            int pos = l0 + j - 1;
            float v = 0.f;
            if (pos >= 0 && pos < NL) {
                int cia = ci0 + ci;
                if (cia < NC) {
                    v = codes[((size_t)b * NC + cia) * NL + pos];
                } else {
                    int f = cia - NC;
                    int fe = (f < 9) ? f : f - 9;
                    float ang = (PIF / (float)(1 << fe)) * (float)pos;
                    v = (f < 9) ? sinf(ang) : cosf(ang);
                }
            }
            xtr[ci * 132 + j] = v;
            xta[ci * 132 + j] = lrelu(v);
        }
        for (int idx = tid; idx < cs * 64; idx += 256) {
            int co = idx & 63, ci = idx >> 6;
            const float* wp = w0 + ((size_t)co * CINA + ci0 + ci) * 3;
            w0t[0][ci * 64 + co] = wp[0];
            w0t[1][ci * 64 + co] = wp[1];
            w0t[2][ci * 64 + co] = wp[2];
            wst[ci * 64 + co] = ws[(size_t)co * CINA + ci0 + ci];
        }
        __syncthreads();
        for (int ci = 0; ci < cs; ci++) {
            const float* xr = xta + ci * 132 + lg * 4;
            float4 a4 = *(const float4*)xr;
            float2 a2 = *(const float2*)(xr + 4);
            float aw[6] = {a4.x, a4.y, a4.z, a4.w, a2.x, a2.y};
            unsigned long long ad[6];
#pragma unroll
            for (int j = 0; j < 6; j++) PACKDUP(ad[j], aw[j]);
            const float* rr = xtr + ci * 132 + lg * 4;
            float4 r4 = *(const float4*)rr;
            float2 r2 = *(const float2*)(rr + 4);
            float rw[4] = {r4.y, r4.z, r4.w, r2.x};
            unsigned long long rd[4];
#pragma unroll
            for (int j = 0; j < 4; j++) PACKDUP(rd[j], rw[j]);
#pragma unroll
            for (int t = 0; t < 3; t++) {
                ulonglong2 wa = *(const ulonglong2*)(&w0t[t][ci * 64 + cg * 8]);
                ulonglong2 wb = *(const ulonglong2*)(&w0t[t][ci * 64 + cg * 8 + 4]);
                unsigned long long wp2[4] = {wa.x, wa.y, wb.x, wb.y};
#pragma unroll
                for (int p = 0; p < 4; p++)
#pragma unroll
                    for (int d = 0; d < 4; d++)
                        FMA2(accd[p][d], wp2[p], ad[d + t], accd[p][d]);
            }
            ulonglong2 sa = *(const ulonglong2*)(&wst[ci * 64 + cg * 8]);
            ulonglong2 sb2 = *(const ulonglong2*)(&wst[ci * 64 + cg * 8 + 4]);
            unsigned long long sp[4] = {sa.x, sa.y, sb2.x, sb2.y};
#pragma unroll
            for (int p = 0; p < 4; p++)
#pragma unroll
                for (int d = 0; d < 4; d++)
                    FMA2(accx[p][d], sp[p], rd[d], accx[p][d]);
        }
    }
#pragma unroll
    for (int p = 0; p < 4; p++) {
        int co0 = cg * 8 + 2 * p, co1 = co0 + 1;
        float d0v[4], d1v[4], x0v[4], x1v[4];
#pragma unroll
        for (int d = 0; d < 4; d++) {
            float lo, hi;
            UNPK(lo, hi, accd[p][d]);
            d0v[d] = lo + b0[co0];
            d1v[d] = hi + b0[co1];
            UNPK(lo, hi, accx[p][d]);
            x0v[d] = lo;
            x1v[d] = hi;
        }
        size_t o0 = ((size_t)b * NC + co0) * NL + l0 + lg * 4;
        size_t o1 = ((size_t)b * NC + co1) * NL + l0 + lg * 4;
        *(float4*)&g_d1[o0] = make_float4(d0v[0], d0v[1], d0v[2], d0v[3]);
        *(float4*)&g_d1[o1] = make_float4(d1v[0], d1v[1], d1v[2], d1v[3]);
        *(float4*)&g_xs[o0] = make_float4(x0v[0], x0v[1], x0v[2], x0v[3]);
        *(float4*)&g_xs[o1] = make_float4(x1v[0], x1v[1], x1v[2], x1v[3]);
    }
}

// ---------------- k3 conv cin=64; optional residual base; optional psum epilogue ----------------
__global__ void k_conv3(const float* __restrict__ xin, const float* __restrict__ w,
                        const float* __restrict__ bias, const float* __restrict__ base,
                        float* __restrict__ out, int do_psum) {
    __shared__ float xt[32 * 132];
    __shared__ float wt[3][32 * 64];
    int b = blockIdx.y, l0 = blockIdx.x * 128, tid = threadIdx.x;
    int lg = tid & 31, cg = tid >> 5;
    unsigned long long acc[4][4];
#pragma unroll
    for (int p = 0; p < 4; p++)
#pragma unroll
        for (int d = 0; d < 4; d++) acc[p][d] = 0ull;
    for (int ci0 = 0; ci0 < NC; ci0 += 32) {
        __syncthreads();
        for (int idx = tid; idx < 32 * 130; idx += 256) {
            int ci = idx / 130, j = idx - ci * 130;
            int pos = l0 + j - 1;
            float v = (pos >= 0 && pos < NL) ? xin[((size_t)b * NC + ci0 + ci) * NL + pos] : 0.f;
            xt[ci * 132 + j] = lrelu(v);
        }
        for (int idx = tid; idx < 2048; idx += 256) {
            int co = idx & 63, ci = idx >> 6;
            const float* wp = w + ((size_t)co * NC + ci0 + ci) * 3;
            wt[0][ci * 64 + co] = wp[0];
            wt[1][ci * 64 + co] = wp[1];
            wt[2][ci * 64 + co] = wp[2];
        }
        __syncthreads();
#pragma unroll 2
        for (int ci = 0; ci < 32; ci++) {
            const float* xr = xt + ci * 132 + lg * 4;
            float4 x4 = *(const float4*)xr;
            float2 x2 = *(const float2*)(xr + 4);
            float xw[6] = {x4.x, x4.y, x4.z, x4.w, x2.x, x2.y};
            unsigned long long xd[6];
#pragma unroll
            for (int j = 0; j < 6; j++) PACKDUP(xd[j], xw[j]);
#pragma unroll
            for (int t = 0; t < 3; t++) {
                ulonglong2 wa = *(const ulonglong2*)(&wt[t][ci * 64 + cg * 8]);
                ulonglong2 wb = *(const ulonglong2*)(&wt[t][ci * 64 + cg * 8 + 4]);
                unsigned long long wp2[4] = {wa.x, wa.y, wb.x, wb.y};
#pragma unroll
                for (int p = 0; p < 4; p++)
#pragma unroll
                    for (int d = 0; d < 4; d++)
                        FMA2(acc[p][d], wp2[p], xd[d + t], acc[p][d]);
            }
        }
    }
    float sv[8], qv[8];
#pragma unroll
    for (int p = 0; p < 4; p++) {
        int co0 = cg * 8 + 2 * p, co1 = co0 + 1;
        float v0[4], v1[4];
#pragma unroll
        for (int d = 0; d < 4; d++) {
            float lo, hi;
            UNPK(lo, hi, acc[p][d]);
            v0[d] = lo + bias[co0];
            v1[d] = hi + bias[co1];
        }
        size_t o0 = ((size_t)b * NC + co0) * NL + l0 + lg * 4;
        size_t o1 = ((size_t)b * NC + co1) * NL + l0 + lg * 4;
        float4 f0, f1;
        if (base) {
            float4 b0v = *(const float4*)&base[o0];
            float4 b1v = *(const float4*)&base[o1];
            f0 = make_float4(b0v.x + 0.1f * v0[0], b0v.y + 0.1f * v0[1],
                             b0v.z + 0.1f * v0[2], b0v.w + 0.1f * v0[3]);
            f1 = make_float4(b1v.x + 0.1f * v1[0], b1v.y + 0.1f * v1[1],
                             b1v.z + 0.1f * v1[2], b1v.w + 0.1f * v1[3]);
        } else {
            f0 = make_float4(v0[0], v0[1], v0[2], v0[3]);
            f1 = make_float4(v1[0], v1[1], v1[2], v1[3]);
        }
        *(float4*)&out[o0] = f0;
        *(float4*)&out[o1] = f1;
        if (do_psum) {
            sv[2 * p] = (f0.x + f0.y) + (f0.z + f0.w);
            qv[2 * p] = (f0.x * f0.x + f0.y * f0.y) + (f0.z * f0.z + f0.w * f0.w);
            sv[2 * p + 1] = (f1.x + f1.y) + (f1.z + f1.w);
            qv[2 * p + 1] = (f1.x * f1.x + f1.y * f1.y) + (f1.z * f1.z + f1.w * f1.w);
        }
    }
    if (do_psum) {
#pragma unroll
        for (int i = 0; i < 8; i++) {
#pragma unroll
            for (int o = 16; o; o >>= 1) {
                sv[i] += __shfl_xor_sync(0xffffffffu, sv[i], o);
                qv[i] += __shfl_xor_sync(0xffffffffu, qv[i], o);
            }
        }
        if ((tid & 31) == 0) {
#pragma unroll
            for (int i = 0; i < 8; i++) {
                size_t o = ((size_t)(b * NC + cg * 8 + i)) * 8 + blockIdx.x * 2;
                g_psum[o] = sv[i];
                g_psum[o + 1] = qv[i];
            }
        }
    }
}

// ---------------- separable gradient fill: 16 outputs/thread, 512 threads ----------------
template <int G>
__device__ __forceinline__ void fill_grad(float* __restrict__ xch, const float* __restrict__ xn,
                                          int cibase, int tid) {
    int ci = tid >> 4, sub = tid & 15;
    int ls = (sub >> 2) + 1;
    int d1p = (sub & 3) * 2;
    const float* row0 = xn + (cibase + ci) * 388;
    float R0[8], R1[8];
#pragma unroll
    for (int i = 0; i < 8; i++) { R0[i] = 0.f; R1[i] = 0.f; }
#pragma unroll
    for (int a = 0; a < 3; a++) {
        float c0;
        if (G == 0) {
            if (a == 1) continue;
            c0 = (a == 0) ? -1.f : 1.f;
        } else {
            c0 = (a == 1) ? 2.f : 1.f;
        }
#pragma unroll
        for (int q = 0; q < 4; q++) {
            float e0, e1;
            if (G == 1) {
                e0 = (q == 0) ? -1.f : ((q == 2) ? 1.f : 0.f);
                e1 = (q == 1) ? -1.f : ((q == 3) ? 1.f : 0.f);
            } else {
                e0 = (q == 0 || q == 2) ? 1.f : ((q == 1) ? 2.f : 0.f);
                e1 = (q == 1 || q == 3) ? 1.f : ((q == 2) ? 2.f : 0.f);
            }
            float c00 = c0 * e0, c01 = c0 * e1;
            if (c00 == 0.f && c01 == 0.f) continue;
            int p1 = d1p - 1 + q;
            if ((unsigned)p1 > 7u) continue;
            const float* rp = row0 + (ls - 1 + a) * 64 + p1 * 8;
            float4 u0 = *(const float4*)rp;
            float4 u1 = *(const float4*)(rp + 4);
            float rv[8] = {u0.x, u0.y, u0.z, u0.w, u1.x, u1.y, u1.z, u1.w};
            if (c00 != 0.f) {
#pragma unroll
                for (int i = 0; i < 8; i++) R0[i] = fmaf(c00, rv[i], R0[i]);
            }
            if (c01 != 0.f) {
#pragma unroll
                for (int i = 0; i < 8; i++) R1[i] = fmaf(c01, rv[i], R1[i]);
            }
        }
    }
    float* dst = xch + ci * 256 + sub * 16;
#pragma unroll
    for (int k = 0; k < 2; k++) {
        float o[8];
        if (G == 2) {
            o[0] = (k ? R1[1] : R0[1]);
#pragma unroll
            for (int d = 1; d < 7; d++)
                o[d] = (k ? R1[d + 1] : R0[d + 1]) - (k ? R1[d - 1] : R0[d - 1]);
            o[7] = -(k ? R1[6] : R0[6]);
        } else {
            o[0] = 2.f * (k ? R1[0] : R0[0]) + (k ? R1[1] : R0[1]);
#pragma unroll
            for (int d = 1; d < 7; d++)
                o[d] = (k ? R1[d - 1] : R0[d - 1]) + 2.f * (k ? R1[d] : R0[d]) +
                       (k ? R1[d + 1] : R0[d + 1]);
            o[7] = (k ? R1[6] : R0[6]) + 2.f * (k ? R1[7] : R0[7]);
        }
        *(float4*)(dst + k * 8) =
            make_float4(__sinf(o[0]), __sinf(o[1]), __sinf(o[2]), __sinf(o[3]));
        *(float4*)(dst + k * 8 + 4) =
            make_float4(__sinf(o[4]), __sinf(o[5]), __sinf(o[6]), __sinf(o[7]));
    }
}

// ---------------- fused stats+norm+sobel+dyna + residual + stats partials ----------------
// 512 threads, s-tile 256, grid (2, NB).
// smem floats: xn 64*388=24832 | xch 32*256=8192 | whs2 32*132=4224 | wssu 32*68=2176 | stats 128
// total 39552 floats = 158208 B. phase2 reuse: ht 64*256=16384 | wls 64*68=4352.
__global__ void __launch_bounds__(512, 1) k_dyna(const float* __restrict__ leak_ptr) {
    extern __shared__ float sm[];
    float* xn = sm;
    float* xch = sm + 24832;
    float* whs2 = sm + 33024;
    float* wssu = sm + 37248;
    float* stats_sm = sm + 39424;
    int b = blockIdx.y, bx = blockIdx.x, s0 = bx * 256, tid = threadIdx.x;
    int sb = (tid & 31) * 8, cb = (tid >> 5) * 4;
    const float* pb = g_p + (size_t)b * PT;
    const float* xb = g_x + (size_t)b * NC * NL;

    // stats from psum partials (replaces k_statsred)
    if (tid < 64) {
        const float4* pp = (const float4*)&g_psum[(size_t)(b * NC + tid) * 8];
        float4 v0 = pp[0], v1 = pp[1];
        float S = (v0.x + v0.z) + (v1.x + v1.z);
        float Q = (v0.y + v0.w) + (v1.y + v1.w);
        float mean = S * (1.f / 512.f);
        float var = Q * (1.f / 512.f) - mean * mean;
        stats_sm[2 * tid] = mean;
        stats_sm[2 * tid + 1] = rsqrtf(var + 1e-5f);
    }
    __syncthreads();
    // normalized x tile: 4 own slabs + 1 halo slab each side = 384 entries/channel
    int posbase = bx * 256 - 64;
    for (int idx = tid; idx < 24576; idx += 512) {
        int c = idx / 384, r = idx - c * 384;
        int pos = posbase + r;
        float v = 0.f;
        if (pos >= 0 && pos < NL)
            v = (xb[c * NL + pos] - stats_sm[2 * c]) * stats_sm[2 * c + 1];
        xn[c * 388 + r] = v;
    }
    __syncthreads();

    unsigned long long ah2[4][4], ao2[4][4];
#pragma unroll
    for (int r = 0; r < 4; r++)
#pragma unroll
        for (int q = 0; q < 4; q++) { ah2[r][q] = 0ull; ao2[r][q] = 0ull; }

    for (int ch = 0; ch < 8; ch++) {
        int ci0 = ch * 32;
        for (int idx = tid; idx < 2048; idx += 512) {
            int ci = idx & 31, co = idx >> 5;
            float wh = pb[co * 256 + ci0 + ci];
            *(float2*)(whs2 + ci * 132 + 2 * co) = make_float2(wh, wh);
            wssu[ci * 68 + co] = pb[O_WS + co * 256 + ci0 + ci];
        }
        const float* xsrc;
        int xstride;
        if (ch < 2) {
            xsrc = xn + (ch * 32) * 388 + 64;
            xstride = 388;
        } else {
            int g = (ch >> 1) - 1;
            int cibase = (ch & 1) * 32;
            if (g == 0) fill_grad<0>(xch, xn, cibase, tid);
            else if (g == 1) fill_grad<1>(xch, xn, cibase, tid);
            else fill_grad<2>(xch, xn, cibase, tid);
            xsrc = xch;
            xstride = 256;
        }
        __syncthreads();
#pragma unroll 2
        for (int ci = 0; ci < 32; ci++) {
            ulonglong2 xa = *(const ulonglong2*)(xsrc + ci * xstride + sb);
            ulonglong2 xb2 = *(const ulonglong2*)(xsrc + ci * xstride + sb + 4);
            unsigned long long xp[4] = {xa.x, xa.y, xb2.x, xb2.y};
            ulonglong2 wha = *(const ulonglong2*)(whs2 + ci * 132 + 2 * cb);
            ulonglong2 whb = *(const ulonglong2*)(whs2 + ci * 132 + 2 * cb + 4);
            unsigned long long wh2[4] = {wha.x, wha.y, whb.x, whb.y};
            float4 wsv = *(const float4*)(wssu + ci * 68 + cb);
            float wsf[4] = {wsv.x, wsv.y, wsv.z, wsv.w};
            unsigned long long ws2[4];
#pragma unroll
            for (int r = 0; r < 4; r++) PACKDUP(ws2[r], wsf[r]);
#pragma unroll
            for (int r = 0; r < 4; r++)
#pragma unroll
                for (int q = 0; q < 4; q++) {
                    FMA2(ah2[r][q], wh2[r], xp[q], ah2[r][q]);
                    FMA2(ao2[r][q], ws2[r], xp[q], ao2[r][q]);
                }
        }
        __syncthreads();
    }

    // phase 2: h = leaky(ah + bh), wl GEMM
    float* ht = sm;            // 64*256
    float* wls = sm + 16384;   // 64*68
#pragma unroll
    for (int r = 0; r < 4; r++) {
        float bh = pb[O_BH + cb + r];
#pragma unroll
        for (int q = 0; q < 4; q++) {
            float lo, hi;
            UNPK(lo, hi, ah2[r][q]);
            ht[(cb + r) * 256 + sb + 2 * q] = lrelu(lo + bh);
            ht[(cb + r) * 256 + sb + 2 * q + 1] = lrelu(hi + bh);
        }
    }
    for (int idx = tid; idx < 4096; idx += 512)
        wls[(idx & 63) * 68 + (idx >> 6)] = pb[O_WL + (idx >> 6) * 64 + (idx & 63)];
    unsigned long long al2[4][4];
#pragma unroll
    for (int r = 0; r < 4; r++)
#pragma unroll
        for (int q = 0; q < 4; q++) al2[r][q] = 0ull;
    __syncthreads();
#pragma unroll 4
    for (int hh = 0; hh < 64; hh++) {
        ulonglong2 ha = *(const ulonglong2*)(ht + hh * 256 + sb);
        ulonglong2 hb2 = *(const ulonglong2*)(ht + hh * 256 + sb + 4);
        unsigned long long hp[4] = {ha.x, ha.y, hb2.x, hb2.y};
        float4 wl4 = *(const float4*)(wls + hh * 68 + cb);
        float wlf[4] = {wl4.x, wl4.y, wl4.z, wl4.w};
#pragma unroll
        for (int r = 0; r < 4; r++) {
            unsigned long long w2;
            PACKDUP(w2, wlf[r]);
#pragma unroll
            for (int q = 0; q < 4; q++) FMA2(al2[r][q], w2, hp[q], al2[r][q]);
        }
    }
    float leak = fminf(fmaxf(*leak_ptr, 0.001f), 1000.f);
    float sv[4], qv[4];
#pragma unroll
    for (int r = 0; r < 4; r++) {
        int co = cb + r;
        float bs = pb[O_BS + co], bl = pb[O_BL + co];
        float* xp_ = g_x + ((size_t)b * NC + co) * NL + s0 + sb;
        float4 o0 = *(float4*)xp_;
        float4 o1 = *(float4*)(xp_ + 4);
        float ov[8] = {o0.x, o0.y, o0.z, o0.w, o1.x, o1.y, o1.z, o1.w};
#pragma unroll
        for (int q = 0; q < 4; q++) {
            float so, sh, dl, dh;
            UNPK(so, sh, ao2[r][q]);
            UNPK(dl, dh, al2[r][q]);
            ov[2 * q] += leak * (so + bs + 0.1f * (dl + bl));
            ov[2 * q + 1] += leak * (sh + bs + 0.1f * (dh + bl));
        }
        *(float4*)xp_ = make_float4(ov[0], ov[1], ov[2], ov[3]);
        *(float4*)(xp_ + 4) = make_float4(ov[4], ov[5], ov[6], ov[7]);
        sv[r] = ((ov[0] + ov[1]) + (ov[2] + ov[3])) + ((ov[4] + ov[5]) + (ov[6] + ov[7]));
        qv[r] = ((ov[0] * ov[0] + ov[1] * ov[1]) + (ov[2] * ov[2] + ov[3] * ov[3])) +
                ((ov[4] * ov[4] + ov[5] * ov[5]) + (ov[6] * ov[6] + ov[7] * ov[7]));
    }
    // warp covers all 256 s for its cb group -> full-warp reduction
#pragma unroll
    for (int r = 0; r < 4; r++) {
#pragma unroll
        for (int o = 16; o; o >>= 1) {
            sv[r] += __shfl_xor_sync(0xffffffffu, sv[r], o);
            qv[r] += __shfl_xor_sync(0xffffffffu, qv[r], o);
        }
    }
    if ((tid & 31) == 0) {
#pragma unroll
        for (int r = 0; r < 4; r++) {
            size_t o = ((size_t)(b * NC + cb + r)) * 8 + bx * 2;
            g_psum[o] = sv[r];
            g_psum[o + 1] = qv[r];
            g_psum[o + 4] = 0.f;
            g_psum[o + 5] = 0.f;
        }
    }
}

// ---------------- CE loss partials ----------------
__global__ void k_loss(const float* __restrict__ codes) {
    __shared__ float xt[64 * 64];
    __shared__ float ct[64 * 64];
    __shared__ float red[8];
    int b = blockIdx.y, l0 = blockIdx.x * 64, tid = threadIdx.x;
    for (int idx = tid; idx < 4096; idx += 256) {
        int c = idx >> 6, lw = idx & 63;
        xt[idx] = g_xs[((size_t)b * NC + c) * NL + l0 + lw];
        ct[idx] = codes[((size_t)b * NC + c) * NL + l0 + lw];
    }
    __syncthreads();
    float mysum = 0.f;
    if (tid < 64) {
        int l = tid;
        float m = xt[l];
        for (int c = 1; c < 64; c++) m = fmaxf(m, xt[c * 64 + l]);
        float se = 0.f;
        for (int c = 0; c < 64; c++) se += expf(xt[c * 64 + l] - m);
        float cm = ct[l];
        int ci = 0;
        for (int c = 1; c < 64; c++) {
            float v = ct[c * 64 + l];
            if (v > cm) { cm = v; ci = c; }
        }
        mysum = -(xt[ci * 64 + l] - m - logf(se));
    }
#pragma unroll
    for (int o = 16; o; o >>= 1) mysum += __shfl_xor_sync(0xffffffffu, mysum, o);
    if ((tid & 31) == 0) red[tid >> 5] = mysum;
    __syncthreads();
    if (tid < 8) {
        float t = red[tid];
#pragma unroll
        for (int o = 4; o; o >>= 1) t += __shfl_xor_sync(0xffu, t, o, 8);
        if (tid == 0) g_part[b * 8 + blockIdx.x] = t;
    }
}

__global__ void k_loss_final(float* __restrict__ out) {
    __shared__ float red[16];
    int t = threadIdx.x;
    float s = g_part[t] + g_part[t + 512] + g_part[t + 1024] + g_part[t + 1536];
#pragma unroll
    for (int o = 16; o; o >>= 1) s += __shfl_xor_sync(0xffffffffu, s, o);
    if ((t & 31) == 0) red[t >> 5] = s;
    __syncthreads();
    if (t < 16) {
        float v = red[t];
#pragma unroll
        for (int o = 8; o; o >>= 1) v += __shfl_xor_sync(0xffffu, v, o, 16);
        if (t == 0) out[131072] = v * (1.f / 131072.f);
    }
}

// ---------------- lat head ----------------
__global__ void k_lat(const float* __restrict__ w0, const float* __restrict__ b0,
                      const float* __restrict__ w1, const float* __restrict__ b1,
                      const float* __restrict__ l2w0, const float* __restrict__ l2b0,
                      const float* __restrict__ l2w1, const float* __restrict__ l2b1,
                      const float* __restrict__ l2ws, float* __restrict__ out) {
    extern __shared__ float sm[];
    float* xt = sm;
    float* ht = sm + 4096;
    float* wb = sm + 8192;
    float* rp = sm;
    int b = blockIdx.y, l0 = blockIdx.x * 64, tid = threadIdx.x;
    int l = tid & 63, cg = tid >> 6;
    for (int idx = tid; idx < 4096; idx += 256) {
        int c = idx >> 6, ll = idx & 63;
        xt[idx] = g_xs[((size_t)b * NC + c) * NL + l0 + ll];
        wb[c * 64 + ll] = w0[ll * 64 + c];
    }
    __syncthreads();
    float acc[16];
#pragma unroll
    for (int r = 0; r < 16; r++) acc[r] = 0.f;
    for (int ci = 0; ci < 64; ci++) {
        float a = lrelu(xt[ci * 64 + l]);
        const float* wr = &wb[ci * 64 + cg * 16];
#pragma unroll
        for (int r = 0; r < 16; r++) acc[r] = fmaf(wr[r], a, acc[r]);
    }
#pragma unroll
    for (int r = 0; r < 16; r++) ht[(cg * 16 + r) * 64 + l] = acc[r] + b0[cg * 16 + r];
    __syncthreads();
    for (int idx = tid; idx < 4096; idx += 256)
        wb[(idx >> 6) * 64 + (idx & 63)] = w1[(idx & 63) * 64 + (idx >> 6)];
    __syncthreads();
#pragma unroll
    for (int r = 0; r < 16; r++) acc[r] = 0.f;
    for (int ci = 0; ci < 64; ci++) {
        float a = lrelu(ht[ci * 64 + l]);
        const float* wr = &wb[ci * 64 + cg * 16];
#pragma unroll
        for (int r = 0; r < 16; r++) acc[r] = fmaf(wr[r], a, acc[r]);
    }
    float lat1v[16];
#pragma unroll
    for (int r = 0; r < 16; r++)
        lat1v[r] = xt[(cg * 16 + r) * 64 + l] + 0.1f * (acc[r] + b1[cg * 16 + r]);
    __syncthreads();
#pragma unroll
    for (int r = 0; r < 16; r++) ht[(cg * 16 + r) * 64 + l] = lat1v[r];
    __syncthreads();
    float s1 = 0.f, s2 = 0.f;
#pragma unroll
    for (int k = 0; k < 16; k++) {
        int ci = cg * 16 + k;
        float v = ht[ci * 64 + l];
        s1 += l2ws[ci] * v;
        s2 += l2w0[ci] * lrelu(v);
    }
    rp[cg * 64 + l] = s1;
    rp[256 + cg * 64 + l] = s2;
    __syncthreads();
    if (tid < 64) {
        float S1 = rp[tid] + rp[64 + tid] + rp[128 + tid] + rp[192 + tid];
        float S2 = rp[256 + tid] + rp[320 + tid] + rp[384 + tid] + rp[448 + tid];
        float dd = l2b0[0] + S2;
        out[(size_t)b * NL + l0 + tid] = S1 + 0.1f * (l2b1[0] + l2w1[0] * lrelu(dd));
    }
}

extern "C" void kernel_launch(void* const* d_in, const int* in_sizes, int n_in,
                              void* d_out, int out_size) {
    const float* codes  = (const float*)d_in[0];
    const int*   y      = (const int*)d_in[1];
    const float* fc_w   = (const float*)d_in[2];
    const float* fc_b   = (const float*)d_in[3];
    const float* in_w0  = (const float*)d_in[4];
    const float* in_b0  = (const float*)d_in[5];
    const float* in_w1  = (const float*)d_in[6];
    const float* in_b1  = (const float*)d_in[7];
    const float* in_ws  = (const float*)d_in[8];
    const float* leak   = (const float*)d_in[9];
    const float* hyper_w = (const float*)d_in[10];
    const float* hyper_b = (const float*)d_in[11];
    const float* out_w0 = (const float*)d_in[12];
    const float* out_b0 = (const float*)d_in[13];
    const float* out_w1 = (const float*)d_in[14];
    const float* out_b1 = (const float*)d_in[15];
    const float* l1_w0  = (const float*)d_in[16];
    const float* l1_b0  = (const float*)d_in[17];
    const float* l1_w1  = (const float*)d_in[18];
    const float* l1_b1  = (const float*)d_in[19];
    const float* l2_w0  = (const float*)d_in[20];
    const float* l2_b0  = (const float*)d_in[21];
    const float* l2_w1  = (const float*)d_in[22];
    const float* l2_b1  = (const float*)d_in[23];
    const float* l2_ws  = (const float*)d_in[24];
    float* out = (float*)d_out;

    float *px, *pxs, *pd1;
    cudaGetSymbolAddress((void**)&px, g_x);
    cudaGetSymbolAddress((void**)&pxs, g_xs);
    cudaGetSymbolAddress((void**)&pd1, g_d1);

    cudaFuncSetAttribute(k_dyna, cudaFuncAttributeMaxDynamicSharedMemorySize, 158208);
    cudaFuncSetAttribute(k_lat, cudaFuncAttributeMaxDynamicSharedMemorySize, 49152);

    k_yemb<<<NB, 256>>>(fc_w, fc_b, y);
    k_pgemm<<<dim3(PT / 64, NB / 64), 256>>>(hyper_w, hyper_b);
    k_conv_in<<<dim3(4, NB), 256>>>(codes, in_w0, in_b0, in_ws);
    k_conv3<<<dim3(4, NB), 256>>>(pd1, in_w1, in_b1, pxs, px, 1);
    for (int it = 0; it < 8; it++) {
        k_dyna<<<dim3(2, NB), 512, 158208>>>(leak);
    }
    k_conv3<<<dim3(4, NB), 256>>>(px, out_w0, out_b0, nullptr, pd1, 0);
    k_conv3<<<dim3(4, NB), 256>>>(pd1, out_w1, out_b1, px, pxs, 0);
    k_loss<<<dim3(8, NB), 256>>>(codes);
    k_loss_final<<<1, 512>>>(out);
    k_lat<<<dim3(8, NB), 256, 49152>>>(l1_w0, l1_b0, l1_w1, l1_b1,
                                       l2_w0, l2_b0, l2_w1, l2_b1, l2_ws, out);
}

// round 12
// speedup vs baseline: 1.1189x; 1.1189x over previous
#include <cuda_runtime.h>
#include <math.h>

#define NB 256
#define NC 64
#define NL 512
#define NLABS 10
#define EMBD 256
#define CINA 82
#define PT 37056
#define O_BH 16384
#define O_WL 16448
#define O_BL 20544
#define O_WS 20608
#define O_BS 36992
#define PIF 3.14159274101257324f

__device__ float g_yemb[NB * EMBD];
__device__ float g_p[(size_t)NB * PT];
__device__ float g_x[(size_t)NB * NC * NL];
__device__ float g_xs[(size_t)NB * NC * NL];
__device__ float g_d1[(size_t)NB * NC * NL];
__device__ float g_psum[NB * NC * 8];
__device__ float g_part[2048];

__device__ __forceinline__ float lrelu(float v) { return v > 0.f ? v : 0.2f * v; }

#define FMA2(d, a, b, c) asm("fma.rn.f32x2 %0, %1, %2, %3;" : "=l"(d) : "l"(a), "l"(b), "l"(c))
#define PACKDUP(d, f) { unsigned int _u = __float_as_uint(f); asm("mov.b64 %0, {%1, %2};" : "=l"(d) : "r"(_u), "r"(_u)); }
#define UNPK(lo, hi, v) { unsigned int _a, _b; asm("mov.b64 {%0, %1}, %2;" : "=r"(_a), "=r"(_b) : "l"(v)); lo = __uint_as_float(_a); hi = __uint_as_float(_b); }

// ---------------- yemb ----------------
__global__ void k_yemb(const float* __restrict__ fc_w, const float* __restrict__ fc_b,
                       const int* __restrict__ y) {
    int b = blockIdx.x, e = threadIdx.x;
    __shared__ float red[8];
    int lab = y[b];
    float v = fc_w[e * NLABS + lab] + fc_b[e];
    float ss = v * v;
#pragma unroll
    for (int o = 16; o; o >>= 1) ss += __shfl_xor_sync(0xffffffffu, ss, o);
    if ((e & 31) == 0) red[e >> 5] = ss;
    __syncthreads();
    if (e < 8) {
        float t = red[e];
#pragma unroll
        for (int o = 4; o; o >>= 1) t += __shfl_xor_sync(0xffu, t, o, 8);
        if (e == 0) red[0] = t;
    }
    __syncthreads();
    float nrm = fmaxf(sqrtf(red[0]), 1e-12f);
    g_yemb[b * EMBD + e] = v / nrm;
}

// ---------------- p = yemb @ hyper_w^T + hyper_b ----------------
__global__ void k_pgemm(const float* __restrict__ hw, const float* __restrict__ hb) {
    __shared__ float ys[64 * 65];
    __shared__ float wst[64 * 68];
    int j0 = blockIdx.x * 64, b0 = blockIdx.y * 64, tid = threadIdx.x;
    int jb = (tid & 15) * 4, bb = (tid >> 4) * 4;
    unsigned long long acc2[4][2];
#pragma unroll
    for (int v = 0; v < 4; v++) { acc2[v][0] = 0ull; acc2[v][1] = 0ull; }
    for (int e0 = 0; e0 < EMBD; e0 += 64) {
        __syncthreads();
        for (int idx = tid; idx < 4096; idx += 256) {
            int r = idx >> 6, e = idx & 63;
            ys[r * 65 + e] = g_yemb[(b0 + r) * EMBD + e0 + e];
            wst[e * 68 + r] = hw[(size_t)(j0 + r) * EMBD + e0 + e];
        }
        __syncthreads();
#pragma unroll 4
        for (int e = 0; e < 64; e++) {
            ulonglong2 wp = *(const ulonglong2*)(wst + e * 68 + jb);
#pragma unroll
            for (int v = 0; v < 4; v++) {
                unsigned long long y2;
                PACKDUP(y2, ys[(bb + v) * 65 + e]);
                FMA2(acc2[v][0], y2, wp.x, acc2[v][0]);
                FMA2(acc2[v][1], y2, wp.y, acc2[v][1]);
            }
        }
    }
#pragma unroll
    for (int v = 0; v < 4; v++) {
#pragma unroll
        for (int q = 0; q < 2; q++) {
            float lo, hi;
            UNPK(lo, hi, acc2[v][q]);
            size_t o = (size_t)(b0 + bb + v) * PT + j0 + jb + 2 * q;
            g_p[o] = lo + hb[j0 + jb + 2 * q];
            g_p[o + 1] = hi + hb[j0 + jb + 2 * q + 1];
        }
    }
}

// ---------------- fused input stage ----------------
__global__ void k_conv_in(const float* __restrict__ codes, const float* __restrict__ w0,
                          const float* __restrict__ b0, const float* __restrict__ ws) {
    __shared__ float xtr[16 * 132];
    __shared__ float xta[16 * 132];
    __shared__ float w0t[3][16 * 64];
    __shared__ float wst[16 * 64];
    int b = blockIdx.y, l0 = blockIdx.x * 128, tid = threadIdx.x;
    int lg = tid & 31, cg = tid >> 5;
    unsigned long long accd[4][4], accx[4][4];
#pragma unroll
    for (int p = 0; p < 4; p++)
#pragma unroll
        for (int d = 0; d < 4; d++) { accd[p][d] = 0ull; accx[p][d] = 0ull; }
    for (int ci0 = 0; ci0 < CINA; ci0 += 16) {
        int cs = min(16, CINA - ci0);
        __syncthreads();
        for (int idx = tid; idx < cs * 130; idx += 256) {
            int ci = idx / 130, j = idx - ci * 130;
            int pos = l0 + j - 1;
            float v = 0.f;
            if (pos >= 0 && pos < NL) {
                int cia = ci0 + ci;
                if (cia < NC) {
                    v = codes[((size_t)b * NC + cia) * NL + pos];
                } else {
                    int f = cia - NC;
                    int fe = (f < 9) ? f : f - 9;
                    float ang = (PIF / (float)(1 << fe)) * (float)pos;
                    v = (f < 9) ? sinf(ang) : cosf(ang);
                }
            }
            xtr[ci * 132 + j] = v;
            xta[ci * 132 + j] = lrelu(v);
        }
        for (int idx = tid; idx < cs * 64; idx += 256) {
            int co = idx & 63, ci = idx >> 6;
            const float* wp = w0 + ((size_t)co * CINA + ci0 + ci) * 3;
            w0t[0][ci * 64 + co] = wp[0];
            w0t[1][ci * 64 + co] = wp[1];
            w0t[2][ci * 64 + co] = wp[2];
            wst[ci * 64 + co] = ws[(size_t)co * CINA + ci0 + ci];
        }
        __syncthreads();
        for (int ci = 0; ci < cs; ci++) {
            const float* xr = xta + ci * 132 + lg * 4;
            float4 a4 = *(const float4*)xr;
            float2 a2 = *(const float2*)(xr + 4);
            float aw[6] = {a4.x, a4.y, a4.z, a4.w, a2.x, a2.y};
            unsigned long long ad[6];
#pragma unroll
            for (int j = 0; j < 6; j++) PACKDUP(ad[j], aw[j]);
            const float* rr = xtr + ci * 132 + lg * 4;
            float4 r4 = *(const float4*)rr;
            float2 r2 = *(const float2*)(rr + 4);
            float rw[4] = {r4.y, r4.z, r4.w, r2.x};
            unsigned long long rd[4];
#pragma unroll
            for (int j = 0; j < 4; j++) PACKDUP(rd[j], rw[j]);
#pragma unroll
            for (int t = 0; t < 3; t++) {
                ulonglong2 wa = *(const ulonglong2*)(&w0t[t][ci * 64 + cg * 8]);
                ulonglong2 wb = *(const ulonglong2*)(&w0t[t][ci * 64 + cg * 8 + 4]);
                unsigned long long wp2[4] = {wa.x, wa.y, wb.x, wb.y};
#pragma unroll
                for (int p = 0; p < 4; p++)
#pragma unroll
                    for (int d = 0; d < 4; d++)
                        FMA2(accd[p][d], wp2[p], ad[d + t], accd[p][d]);
            }
            ulonglong2 sa = *(const ulonglong2*)(&wst[ci * 64 + cg * 8]);
            ulonglong2 sb2 = *(const ulonglong2*)(&wst[ci * 64 + cg * 8 + 4]);
            unsigned long long sp[4] = {sa.x, sa.y, sb2.x, sb2.y};
#pragma unroll
            for (int p = 0; p < 4; p++)
#pragma unroll
                for (int d = 0; d < 4; d++)
                    FMA2(accx[p][d], sp[p], rd[d], accx[p][d]);
        }
    }
#pragma unroll
    for (int p = 0; p < 4; p++) {
        int co0 = cg * 8 + 2 * p, co1 = co0 + 1;
        float d0v[4], d1v[4], x0v[4], x1v[4];
#pragma unroll
        for (int d = 0; d < 4; d++) {
            float lo, hi;
            UNPK(lo, hi, accd[p][d]);
            d0v[d] = lo + b0[co0];
            d1v[d] = hi + b0[co1];
            UNPK(lo, hi, accx[p][d]);
            x0v[d] = lo;
            x1v[d] = hi;
        }
        size_t o0 = ((size_t)b * NC + co0) * NL + l0 + lg * 4;
        size_t o1 = ((size_t)b * NC + co1) * NL + l0 + lg * 4;
        *(float4*)&g_d1[o0] = make_float4(d0v[0], d0v[1], d0v[2], d0v[3]);
        *(float4*)&g_d1[o1] = make_float4(d1v[0], d1v[1], d1v[2], d1v[3]);
        *(float4*)&g_xs[o0] = make_float4(x0v[0], x0v[1], x0v[2], x0v[3]);
        *(float4*)&g_xs[o1] = make_float4(x1v[0], x1v[1], x1v[2], x1v[3]);
    }
}

// ---------------- k3 conv cin=64; optional residual base; optional psum epilogue ----------------
__global__ void k_conv3(const float* __restrict__ xin, const float* __restrict__ w,
                        const float* __restrict__ bias, const float* __restrict__ base,
                        float* __restrict__ out, int do_psum) {
    __shared__ float xt[32 * 132];
    __shared__ float wt[3][32 * 64];
    int b = blockIdx.y, l0 = blockIdx.x * 128, tid = threadIdx.x;
    int lg = tid & 31, cg = tid >> 5;
    unsigned long long acc[4][4];
#pragma unroll
    for (int p = 0; p < 4; p++)
#pragma unroll
        for (int d = 0; d < 4; d++) acc[p][d] = 0ull;
    for (int ci0 = 0; ci0 < NC; ci0 += 32) {
        __syncthreads();
        for (int idx = tid; idx < 32 * 130; idx += 256) {
            int ci = idx / 130, j = idx - ci * 130;
            int pos = l0 + j - 1;
            float v = (pos >= 0 && pos < NL) ? xin[((size_t)b * NC + ci0 + ci) * NL + pos] : 0.f;
            xt[ci * 132 + j] = lrelu(v);
        }
        for (int idx = tid; idx < 2048; idx += 256) {
            int co = idx & 63, ci = idx >> 6;
            const float* wp = w + ((size_t)co * NC + ci0 + ci) * 3;
            wt[0][ci * 64 + co] = wp[0];
            wt[1][ci * 64 + co] = wp[1];
            wt[2][ci * 64 + co] = wp[2];
        }
        __syncthreads();
#pragma unroll 2
        for (int ci = 0; ci < 32; ci++) {
            const float* xr = xt + ci * 132 + lg * 4;
            float4 x4 = *(const float4*)xr;
            float2 x2 = *(const float2*)(xr + 4);
            float xw[6] = {x4.x, x4.y, x4.z, x4.w, x2.x, x2.y};
            unsigned long long xd[6];
#pragma unroll
            for (int j = 0; j < 6; j++) PACKDUP(xd[j], xw[j]);
#pragma unroll
            for (int t = 0; t < 3; t++) {
                ulonglong2 wa = *(const ulonglong2*)(&wt[t][ci * 64 + cg * 8]);
                ulonglong2 wb = *(const ulonglong2*)(&wt[t][ci * 64 + cg * 8 + 4]);
                unsigned long long wp2[4] = {wa.x, wa.y, wb.x, wb.y};
#pragma unroll
                for (int p = 0; p < 4; p++)
#pragma unroll
                    for (int d = 0; d < 4; d++)
                        FMA2(acc[p][d], wp2[p], xd[d + t], acc[p][d]);
            }
        }
    }
    float sv[8], qv[8];
#pragma unroll
    for (int p = 0; p < 4; p++) {
        int co0 = cg * 8 + 2 * p, co1 = co0 + 1;
        float v0[4], v1[4];
#pragma unroll
        for (int d = 0; d < 4; d++) {
            float lo, hi;
            UNPK(lo, hi, acc[p][d]);
            v0[d] = lo + bias[co0];
            v1[d] = hi + bias[co1];
        }
        size_t o0 = ((size_t)b * NC + co0) * NL + l0 + lg * 4;
        size_t o1 = ((size_t)b * NC + co1) * NL + l0 + lg * 4;
        float4 f0, f1;
        if (base) {
            float4 b0v = *(const float4*)&base[o0];
            float4 b1v = *(const float4*)&base[o1];
            f0 = make_float4(b0v.x + 0.1f * v0[0], b0v.y + 0.1f * v0[1],
                             b0v.z + 0.1f * v0[2], b0v.w + 0.1f * v0[3]);
            f1 = make_float4(b1v.x + 0.1f * v1[0], b1v.y + 0.1f * v1[1],
                             b1v.z + 0.1f * v1[2], b1v.w + 0.1f * v1[3]);
        } else {
            f0 = make_float4(v0[0], v0[1], v0[2], v0[3]);
            f1 = make_float4(v1[0], v1[1], v1[2], v1[3]);
        }
        *(float4*)&out[o0] = f0;
        *(float4*)&out[o1] = f1;
        if (do_psum) {
            sv[2 * p] = (f0.x + f0.y) + (f0.z + f0.w);
            qv[2 * p] = (f0.x * f0.x + f0.y * f0.y) + (f0.z * f0.z + f0.w * f0.w);
            sv[2 * p + 1] = (f1.x + f1.y) + (f1.z + f1.w);
            qv[2 * p + 1] = (f1.x * f1.x + f1.y * f1.y) + (f1.z * f1.z + f1.w * f1.w);
        }
    }
    if (do_psum) {
#pragma unroll
        for (int i = 0; i < 8; i++) {
#pragma unroll
            for (int o = 16; o; o >>= 1) {
                sv[i] += __shfl_xor_sync(0xffffffffu, sv[i], o);
                qv[i] += __shfl_xor_sync(0xffffffffu, qv[i], o);
            }
        }
        if ((tid & 31) == 0) {
#pragma unroll
            for (int i = 0; i < 8; i++) {
                size_t o = ((size_t)(b * NC + cg * 8 + i)) * 8 + blockIdx.x * 2;
                g_psum[o] = sv[i];
                g_psum[o + 1] = qv[i];
            }
        }
    }
}

// ---------------- separable gradient fill: 16 outputs/thread, 256 threads ----------------
template <int G>
__device__ __forceinline__ void fill_grad(float* __restrict__ xch, const float* __restrict__ xn,
                                          int cibase, int tid) {
    int ci = tid >> 3, sub = tid & 7;
    int ls = (sub >> 2) + 1;
    int d1p = (sub & 3) * 2;
    const float* row0 = xn + (cibase + ci) * 260;
    float R0[8], R1[8];
#pragma unroll
    for (int i = 0; i < 8; i++) { R0[i] = 0.f; R1[i] = 0.f; }
#pragma unroll
    for (int a = 0; a < 3; a++) {
        float c0;
        if (G == 0) {
            if (a == 1) continue;
            c0 = (a == 0) ? -1.f : 1.f;
        } else {
            c0 = (a == 1) ? 2.f : 1.f;
        }
#pragma unroll
        for (int q = 0; q < 4; q++) {
            float e0, e1;
            if (G == 1) {
                e0 = (q == 0) ? -1.f : ((q == 2) ? 1.f : 0.f);
                e1 = (q == 1) ? -1.f : ((q == 3) ? 1.f : 0.f);
            } else {
                e0 = (q == 0 || q == 2) ? 1.f : ((q == 1) ? 2.f : 0.f);
                e1 = (q == 1 || q == 3) ? 1.f : ((q == 2) ? 2.f : 0.f);
            }
            float c00 = c0 * e0, c01 = c0 * e1;
            if (c00 == 0.f && c01 == 0.f) continue;
            int p1 = d1p - 1 + q;
            if ((unsigned)p1 > 7u) continue;
            const float* rp = row0 + (ls - 1 + a) * 64 + p1 * 8;
            float4 u0 = *(const float4*)rp;
            float4 u1 = *(const float4*)(rp + 4);
            float rv[8] = {u0.x, u0.y, u0.z, u0.w, u1.x, u1.y, u1.z, u1.w};
            if (c00 != 0.f) {
#pragma unroll
                for (int i = 0; i < 8; i++) R0[i] = fmaf(c00, rv[i], R0[i]);
            }
            if (c01 != 0.f) {
#pragma unroll
                for (int i = 0; i < 8; i++) R1[i] = fmaf(c01, rv[i], R1[i]);
            }
        }
    }
    float* dst = xch + ci * 128 + sub * 16;
#pragma unroll
    for (int k = 0; k < 2; k++) {
        float o[8];
        if (G == 2) {
            o[0] = (k ? R1[1] : R0[1]);
#pragma unroll
            for (int d = 1; d < 7; d++)
                o[d] = (k ? R1[d + 1] : R0[d + 1]) - (k ? R1[d - 1] : R0[d - 1]);
            o[7] = -(k ? R1[6] : R0[6]);
        } else {
            o[0] = 2.f * (k ? R1[0] : R0[0]) + (k ? R1[1] : R0[1]);
#pragma unroll
            for (int d = 1; d < 7; d++)
                o[d] = (k ? R1[d - 1] : R0[d - 1]) + 2.f * (k ? R1[d] : R0[d]) +
                       (k ? R1[d + 1] : R0[d + 1]);
            o[7] = (k ? R1[6] : R0[6]) + 2.f * (k ? R1[7] : R0[7]);
        }
        *(float4*)(dst + k * 8) =
            make_float4(__sinf(o[0]), __sinf(o[1]), __sinf(o[2]), __sinf(o[3]));
        *(float4*)(dst + k * 8 + 4) =
            make_float4(__sinf(o[4]), __sinf(o[5]), __sinf(o[6]), __sinf(o[7]));
    }
}

// ---------------- fused stats+norm+sobel+dyna + residual + stats partials ----------------
// 256 threads, s-tile 128, grid (4, NB), 2 blocks/SM (R9 shape).
// smem floats: xn 64*260=16640 | xch 4096 | whs2 32*132=4224 | wssu 32*68=2176 | stats 128
__global__ void __launch_bounds__(256, 2) k_dyna(const float* __restrict__ leak_ptr) {
    extern __shared__ float sm[];
    float* xn = sm;
    float* xch = sm + 16640;
    float* whs2 = sm + 20736;
    float* wssu = sm + 24960;
    float* stats_sm = sm + 27136;
    int b = blockIdx.y, s0 = blockIdx.x * 128, tid = threadIdx.x;
    int sb = (tid & 15) * 8, cb = (tid >> 4) * 4;
    const float* pb = g_p + (size_t)b * PT;
    const float* xb = g_x + (size_t)b * NC * NL;

    // stats from psum partials (fused statsred)
    if (tid < 64) {
        const float4* pp = (const float4*)&g_psum[(size_t)(b * NC + tid) * 8];
        float4 v0 = pp[0], v1 = pp[1];
        float S = (v0.x + v0.z) + (v1.x + v1.z);
        float Q = (v0.y + v0.w) + (v1.y + v1.w);
        float mean = S * (1.f / 512.f);
        float var = Q * (1.f / 512.f) - mean * mean;
        stats_sm[2 * tid] = mean;
        stats_sm[2 * tid + 1] = rsqrtf(var + 1e-5f);
    }
    __syncthreads();
    int posbase = ((int)blockIdx.x * 2 - 1) * 64;
    for (int idx = tid; idx < 16384; idx += 256) {
        int c = idx >> 8, r = idx & 255;
        int pos = posbase + r;
        float v = 0.f;
        if (pos >= 0 && pos < NL)
            v = (xb[c * NL + pos] - stats_sm[2 * c]) * stats_sm[2 * c + 1];
        xn[c * 260 + r] = v;
    }
    __syncthreads();

    unsigned long long ah2[4][4], ao2[4][4];
#pragma unroll
    for (int r = 0; r < 4; r++)
#pragma unroll
        for (int q = 0; q < 4; q++) { ah2[r][q] = 0ull; ao2[r][q] = 0ull; }

    for (int ch = 0; ch < 8; ch++) {
        int ci0 = ch * 32;
        for (int idx = tid; idx < 2048; idx += 256) {
            int ci = idx & 31, co = idx >> 5;
            float wh = pb[co * 256 + ci0 + ci];
            *(float2*)(whs2 + ci * 132 + 2 * co) = make_float2(wh, wh);
            wssu[ci * 68 + co] = pb[O_WS + co * 256 + ci0 + ci];
        }
        const float* xsrc;
        int xstride;
        if (ch < 2) {
            xsrc = xn + (ch * 32) * 260 + 64;
            xstride = 260;
        } else {
            int g = (ch >> 1) - 1;
            int cibase = (ch & 1) * 32;
            if (g == 0) fill_grad<0>(xch, xn, cibase, tid);
            else if (g == 1) fill_grad<1>(xch, xn, cibase, tid);
            else fill_grad<2>(xch, xn, cibase, tid);
            xsrc = xch;
            xstride = 128;
        }
        __syncthreads();
#pragma unroll 2
        for (int ci = 0; ci < 32; ci++) {
            ulonglong2 xa = *(const ulonglong2*)(xsrc + ci * xstride + sb);
            ulonglong2 xb2 = *(const ulonglong2*)(xsrc + ci * xstride + sb + 4);
            unsigned long long xp[4] = {xa.x, xa.y, xb2.x, xb2.y};
            ulonglong2 wha = *(const ulonglong2*)(whs2 + ci * 132 + 2 * cb);
            ulonglong2 whb = *(const ulonglong2*)(whs2 + ci * 132 + 2 * cb + 4);
            unsigned long long wh2[4] = {wha.x, wha.y, whb.x, whb.y};
            float4 wsv = *(const float4*)(wssu + ci * 68 + cb);
            float wsf[4] = {wsv.x, wsv.y, wsv.z, wsv.w};
            unsigned long long ws2[4];
#pragma unroll
            for (int r = 0; r < 4; r++) PACKDUP(ws2[r], wsf[r]);
#pragma unroll
            for (int r = 0; r < 4; r++)
#pragma unroll
                for (int q = 0; q < 4; q++) {
                    FMA2(ah2[r][q], wh2[r], xp[q], ah2[r][q]);
                    FMA2(ao2[r][q], ws2[r], xp[q], ao2[r][q]);
                }
        }
        __syncthreads();
    }

    float* ht = sm;
    float* wls = sm + 8192;
#pragma unroll
    for (int r = 0; r < 4; r++) {
        float bh = pb[O_BH + cb + r];
#pragma unroll
        for (int q = 0; q < 4; q++) {
            float lo, hi;
            UNPK(lo, hi, ah2[r][q]);
            ht[(cb + r) * 128 + sb + 2 * q] = lrelu(lo + bh);
            ht[(cb + r) * 128 + sb + 2 * q + 1] = lrelu(hi + bh);
        }
    }
    for (int idx = tid; idx < 4096; idx += 256)
        wls[(idx & 63) * 68 + (idx >> 6)] = pb[O_WL + (idx >> 6) * 64 + (idx & 63)];
    unsigned long long al2[4][4];
#pragma unroll
    for (int r = 0; r < 4; r++)
#pragma unroll
        for (int q = 0; q < 4; q++) al2[r][q] = 0ull;
    __syncthreads();
#pragma unroll 4
    for (int hh = 0; hh < 64; hh++) {
        ulonglong2 ha = *(const ulonglong2*)(ht + hh * 128 + sb);
        ulonglong2 hb2 = *(const ulonglong2*)(ht + hh * 128 + sb + 4);
        unsigned long long hp[4] = {ha.x, ha.y, hb2.x, hb2.y};
        float4 wl4 = *(const float4*)(wls + hh * 68 + cb);
        float wlf[4] = {wl4.x, wl4.y, wl4.z, wl4.w};
#pragma unroll
        for (int r = 0; r < 4; r++) {
            unsigned long long w2;
            PACKDUP(w2, wlf[r]);
#pragma unroll
            for (int q = 0; q < 4; q++) FMA2(al2[r][q], w2, hp[q], al2[r][q]);
        }
    }
    float leak = fminf(fmaxf(*leak_ptr, 0.001f), 1000.f);
    float sv[4], qv[4];
#pragma unroll
    for (int r = 0; r < 4; r++) {
        int co = cb + r;
        float bs = pb[O_BS + co], bl = pb[O_BL + co];
        float* xp_ = g_x + ((size_t)b * NC + co) * NL + s0 + sb;
        float4 o0 = *(float4*)xp_;
        float4 o1 = *(float4*)(xp_ + 4);
        float ov[8] = {o0.x, o0.y, o0.z, o0.w, o1.x, o1.y, o1.z, o1.w};
#pragma unroll
        for (int q = 0; q < 4; q++) {
            float so, sh, dl, dh;
            UNPK(so, sh, ao2[r][q]);
            UNPK(dl, dh, al2[r][q]);
            ov[2 * q] += leak * (so + bs + 0.1f * (dl + bl));
            ov[2 * q + 1] += leak * (sh + bs + 0.1f * (dh + bl));
        }
        *(float4*)xp_ = make_float4(ov[0], ov[1], ov[2], ov[3]);
        *(float4*)(xp_ + 4) = make_float4(ov[4], ov[5], ov[6], ov[7]);
        sv[r] = ((ov[0] + ov[1]) + (ov[2] + ov[3])) + ((ov[4] + ov[5]) + (ov[6] + ov[7]));
        qv[r] = ((ov[0] * ov[0] + ov[1] * ov[1]) + (ov[2] * ov[2] + ov[3] * ov[3])) +
                ((ov[4] * ov[4] + ov[5] * ov[5]) + (ov[6] * ov[6] + ov[7] * ov[7]));
    }
#pragma unroll
    for (int r = 0; r < 4; r++) {
#pragma unroll
        for (int o = 8; o; o >>= 1) {
            sv[r] += __shfl_xor_sync(0xffffffffu, sv[r], o);
            qv[r] += __shfl_xor_sync(0xffffffffu, qv[r], o);
        }
    }
    if ((tid & 15) == 0) {
#pragma unroll
        for (int r = 0; r < 4; r++) {
            size_t o = ((size_t)(b * NC + cb + r)) * 8 + blockIdx.x * 2;
            g_psum[o] = sv[r];
            g_psum[o + 1] = qv[r];
        }
    }
}

// ---------------- CE loss partials ----------------
__global__ void k_loss(const float* __restrict__ codes) {
    __shared__ float xt[64 * 64];
    __shared__ float ct[64 * 64];
    __shared__ float red[8];
    int b = blockIdx.y, l0 = blockIdx.x * 64, tid = threadIdx.x;
    for (int idx = tid; idx < 4096; idx += 256) {
        int c = idx >> 6, lw = idx & 63;
        xt[idx] = g_xs[((size_t)b * NC + c) * NL + l0 + lw];
        ct[idx] = codes[((size_t)b * NC + c) * NL + l0 + lw];
    }
    __syncthreads();
    float mysum = 0.f;
    if (tid < 64) {
        int l = tid;
        float m = xt[l];
        for (int c = 1; c < 64; c++) m = fmaxf(m, xt[c * 64 + l]);
        float se = 0.f;
        for (int c = 0; c < 64; c++) se += expf(xt[c * 64 + l] - m);
        float cm = ct[l];
        int ci = 0;
        for (int c = 1; c < 64; c++) {
            float v = ct[c * 64 + l];
            if (v > cm) { cm = v; ci = c; }
        }
        mysum = -(xt[ci * 64 + l] - m - logf(se));
    }
#pragma unroll
    for (int o = 16; o; o >>= 1) mysum += __shfl_xor_sync(0xffffffffu, mysum, o);
    if ((tid & 31) == 0) red[tid >> 5] = mysum;
    __syncthreads();
    if (tid < 8) {
        float t = red[tid];
#pragma unroll
        for (int o = 4; o; o >>= 1) t += __shfl_xor_sync(0xffu, t, o, 8);
        if (tid == 0) g_part[b * 8 + blockIdx.x] = t;
    }
}

__global__ void k_loss_final(float* __restrict__ out) {
    __shared__ float red[16];
    int t = threadIdx.x;
    float s = g_part[t] + g_part[t + 512] + g_part[t + 1024] + g_part[t + 1536];
#pragma unroll
    for (int o = 16; o; o >>= 1) s += __shfl_xor_sync(0xffffffffu, s, o);
    if ((t & 31) == 0) red[t >> 5] = s;
    __syncthreads();
    if (t < 16) {
        float v = red[t];
#pragma unroll
        for (int o = 8; o; o >>= 1) v += __shfl_xor_sync(0xffffu, v, o, 16);
        if (t == 0) out[131072] = v * (1.f / 131072.f);
    }
}

// ---------------- lat head ----------------
__global__ void k_lat(const float* __restrict__ w0, const float* __restrict__ b0,
                      const float* __restrict__ w1, const float* __restrict__ b1,
                      const float* __restrict__ l2w0, const float* __restrict__ l2b0,
                      const float* __restrict__ l2w1, const float* __restrict__ l2b1,
                      const float* __restrict__ l2ws, float* __restrict__ out) {
    extern __shared__ float sm[];
    float* xt = sm;
    float* ht = sm + 4096;
    float* wb = sm + 8192;
    float* rp = sm;
    int b = blockIdx.y, l0 = blockIdx.x * 64, tid = threadIdx.x;
    int l = tid & 63, cg = tid >> 6;
    for (int idx = tid; idx < 4096; idx += 256) {
        int c = idx >> 6, ll = idx & 63;
        xt[idx] = g_xs[((size_t)b * NC + c) * NL + l0 + ll];
        wb[c * 64 + ll] = w0[ll * 64 + c];
    }
    __syncthreads();
    float acc[16];
#pragma unroll
    for (int r = 0; r < 16; r++) acc[r] = 0.f;
    for (int ci = 0; ci < 64; ci++) {
        float a = lrelu(xt[ci * 64 + l]);
        const float* wr = &wb[ci * 64 + cg * 16];
#pragma unroll
        for (int r = 0; r < 16; r++) acc[r] = fmaf(wr[r], a, acc[r]);
    }
#pragma unroll
    for (int r = 0; r < 16; r++) ht[(cg * 16 + r) * 64 + l] = acc[r] + b0[cg * 16 + r];
    __syncthreads();
    for (int idx = tid; idx < 4096; idx += 256)
        wb[(idx >> 6) * 64 + (idx & 63)] = w1[(idx & 63) * 64 + (idx >> 6)];
    __syncthreads();
#pragma unroll
    for (int r = 0; r < 16; r++) acc[r] = 0.f;
    for (int ci = 0; ci < 64; ci++) {
        float a = lrelu(ht[ci * 64 + l]);
        const float* wr = &wb[ci * 64 + cg * 16];
#pragma unroll
        for (int r = 0; r < 16; r++) acc[r] = fmaf(wr[r], a, acc[r]);
    }
    float lat1v[16];
#pragma unroll
    for (int r = 0; r < 16; r++)
        lat1v[r] = xt[(cg * 16 + r) * 64 + l] + 0.1f * (acc[r] + b1[cg * 16 + r]);
    __syncthreads();
#pragma unroll
    for (int r = 0; r < 16; r++) ht[(cg * 16 + r) * 64 + l] = lat1v[r];
    __syncthreads();
    float s1 = 0.f, s2 = 0.f;
#pragma unroll
    for (int k = 0; k < 16; k++) {
        int ci = cg * 16 + k;
        float v = ht[ci * 64 + l];
        s1 += l2ws[ci] * v;
        s2 += l2w0[ci] * lrelu(v);
    }
    rp[cg * 64 + l] = s1;
    rp[256 + cg * 64 + l] = s2;
    __syncthreads();
    if (tid < 64) {
        float S1 = rp[tid] + rp[64 + tid] + rp[128 + tid] + rp[192 + tid];
        float S2 = rp[256 + tid] + rp[320 + tid] + rp[384 + tid] + rp[448 + tid];
        float dd = l2b0[0] + S2;
        out[(size_t)b * NL + l0 + tid] = S1 + 0.1f * (l2b1[0] + l2w1[0] * lrelu(dd));
    }
}

extern "C" void kernel_launch(void* const* d_in, const int* in_sizes, int n_in,
                              void* d_out, int out_size) {
    const float* codes  = (const float*)d_in[0];
    const int*   y      = (const int*)d_in[1];
    const float* fc_w   = (const float*)d_in[2];
    const float* fc_b   = (const float*)d_in[3];
    const float* in_w0  = (const float*)d_in[4];
    const float* in_b0  = (const float*)d_in[5];
    const float* in_w1  = (const float*)d_in[6];
    const float* in_b1  = (const float*)d_in[7];
    const float* in_ws  = (const float*)d_in[8];
    const float* leak   = (const float*)d_in[9];
    const float* hyper_w = (const float*)d_in[10];
    const float* hyper_b = (const float*)d_in[11];
    const float* out_w0 = (const float*)d_in[12];
    const float* out_b0 = (const float*)d_in[13];
    const float* out_w1 = (const float*)d_in[14];
    const float* out_b1 = (const float*)d_in[15];
    const float* l1_w0  = (const float*)d_in[16];
    const float* l1_b0  = (const float*)d_in[17];
    const float* l1_w1  = (const float*)d_in[18];
    const float* l1_b1  = (const float*)d_in[19];
    const float* l2_w0  = (const float*)d_in[20];
    const float* l2_b0  = (const float*)d_in[21];
    const float* l2_w1  = (const float*)d_in[22];
    const float* l2_b1  = (const float*)d_in[23];
    const float* l2_ws  = (const float*)d_in[24];
    float* out = (float*)d_out;

    float *px, *pxs, *pd1;
    cudaGetSymbolAddress((void**)&px, g_x);
    cudaGetSymbolAddress((void**)&pxs, g_xs);
    cudaGetSymbolAddress((void**)&pd1, g_d1);

    cudaFuncSetAttribute(k_dyna, cudaFuncAttributeMaxDynamicSharedMemorySize, 109056);
    cudaFuncSetAttribute(k_lat, cudaFuncAttributeMaxDynamicSharedMemorySize, 49152);

    k_yemb<<<NB, 256>>>(fc_w, fc_b, y);
    k_pgemm<<<dim3(PT / 64, NB / 64), 256>>>(hyper_w, hyper_b);
    k_conv_in<<<dim3(4, NB), 256>>>(codes, in_w0, in_b0, in_ws);
    k_conv3<<<dim3(4, NB), 256>>>(pd1, in_w1, in_b1, pxs, px, 1);
    for (int it = 0; it < 8; it++) {
        k_dyna<<<dim3(4, NB), 256, 109056>>>(leak);
    }
    k_conv3<<<dim3(4, NB), 256>>>(px, out_w0, out_b0, nullptr, pd1, 0);
    k_conv3<<<dim3(4, NB), 256>>>(pd1, out_w1, out_b1, px, pxs, 0);
    k_loss<<<dim3(8, NB), 256>>>(codes);
    k_loss_final<<<1, 512>>>(out);
    k_lat<<<dim3(8, NB), 256, 49152>>>(l1_w0, l1_b0, l1_w1, l1_b1,
                                       l2_w0, l2_b0, l2_w1, l2_b1, l2_ws, out);
}